// round 6
// baseline (speedup 1.0000x reference)
#include <cuda_runtime.h>
#include <math.h>
#include <stdint.h>

#define Bz 256
#define Sz 64
#define Hz 512
#define Nz 16
#define Lz 2
#define Tz 63
#define ODz 9

// ---------------- device-global scratch (no allocation allowed) ----------------
__device__ float d_encoded[(size_t)Bz * Sz * Hz];     // 33.5 MB
__device__ float d_state[(size_t)Lz * Bz * Hz * Nz];  // 16.8 MB
__device__ float d_g[Bz * Hz];
__device__ float d_y[Bz * Hz];
__device__ float d_ctx[Bz * Hz];
__device__ float d_dpTable[4 * Hz];
__device__ int   d_flag[Bz];

// ---------------- helpers ----------------
// block-wide fp64 sum over 512 threads (one value per thread). red = shared double[16].
__device__ __forceinline__ double block_sum_d(double v, double* red, int tid) {
    int wid = tid >> 5, lane = tid & 31;
#pragma unroll
    for (int o = 16; o > 0; o >>= 1) v += __shfl_xor_sync(0xffffffffu, v, o);
    if (lane == 0) red[wid] = v;
    __syncthreads();
    if (tid < 32) {
        double r = (lane < 16) ? red[lane] : 0.0;
#pragma unroll
        for (int o = 8; o > 0; o >>= 1) r += __shfl_xor_sync(0xffffffffu, r, o);
        if (lane == 0) red[0] = r;
    }
    __syncthreads();
    double r = red[0];
    __syncthreads();  // allow red reuse
    return r;
}

// two-pass LayerNorm, fp64 stats (matches reference mean((x-m)^2) form, near-exact)
__device__ __forceinline__ float ln_norm(float v, float g, float bta, double* red, int tid) {
    double m = block_sum_d((double)v, red, tid) * (1.0 / Hz);
    double d = (double)v - m;
    double var = block_sum_d(d * d, red, tid) * (1.0 / Hz);
    double scale = 1.0 / sqrt(var + 1e-5);
    return (float)(d * scale * (double)g + (double)bta);
}

__device__ __forceinline__ float gelu_exact(float x) {
    return 0.5f * x * (1.0f + erff(x * 0.7071067811865476f));
}

__device__ __forceinline__ void twosum(float& s, float& e, float p) {
    float t = s + p;
    float bp = t - s;
    e += (s - (t - bp)) + (p - bp);
    s = t;
}

// Reference-pipeline fp32 sigmoid: exp in fp32 (libdevice __nv_expf, same as
// XLA:GPU), fp32 add, fp32 divide. Saturates to exactly 1.0f for x >~ 16.64
// and to 0.0f for x <~ -103, reproducing the argmax tie structure.
__device__ __forceinline__ float sigmoid_ref(float x) {
    return 1.0f / (1.0f + expf(-x));
}

// ---------------- init: zero state/ctx/flag, build dp table ----------------
__global__ void init_kernel(const float* __restrict__ in_W, const float* __restrict__ in_b) {
    int i = blockIdx.x * blockDim.x + threadIdx.x;
    const int SS = Lz * Bz * Hz * Nz;
    if (i < SS) d_state[i] = 0.f;
    if (i < Bz * Hz) d_ctx[i] = 0.f;
    if (i < Bz) d_flag[i] = 0;  // dec0 = [0,0,1] -> c=0, tag0=0 -> idx 0
    if (i < 4 * Hz) {
        int v = i >> 9, h = i & 511;
        float c  = (float)(v & 1);
        float t0 = (float)((v >> 1) & 1);
        float s = __fadd_rn(__fadd_rn(__fmul_rn(c, in_W[h]), __fmul_rn(t0, in_W[Hz + h])),
                            __fmul_rn(__fsub_rn(1.f, t0), in_W[2 * Hz + h]));
        d_dpTable[i] = __fadd_rn(s, in_b[h]);
    }
}

// ---------------- encode: encoded = input_seq @ in_W + in_b ----------------
__global__ void encode_kernel(const float* __restrict__ inp,
                              const float* __restrict__ in_W,
                              const float* __restrict__ in_b) {
    size_t i = (size_t)blockIdx.x * 256 + threadIdx.x;
    int h = (int)(i & 511);
    size_t bs = i >> 9;
    const float* p = inp + bs * 3;
    float s = __fadd_rn(__fadd_rn(__fmul_rn(p[0], in_W[h]), __fmul_rn(p[1], in_W[Hz + h])),
                        __fmul_rn(p[2], in_W[2 * Hz + h]));
    d_encoded[i] = __fadd_rn(s, in_b[h]);
}

// ---------------- state kernel: [optional LN of previous y] + S4 step + gelu ----------------
__global__ void state_kernel(int layer, int xdMode, int resMode,
                             const float* __restrict__ A, const float* __restrict__ Bm,
                             const float* __restrict__ Cm, const float* __restrict__ Dp,
                             const float* __restrict__ lng, const float* __restrict__ lnb) {
    int b = blockIdx.x, h = threadIdx.x;
    __shared__ double redd[16];
    float xd;
    if (xdMode == 0) {
        xd = d_dpTable[d_flag[b] * Hz + h];
    } else {
        float y = d_y[b * Hz + h];
        float res = resMode ? d_dpTable[d_flag[b] * Hz + h] : y;
        xd = ln_norm(__fadd_rn(y, res), lng[h], lnb[h], redd, h);  // ln layer 0
    }
    int hh = layer * Hz + h;
    const float4* A4 = (const float4*)(A + (size_t)hh * Nz);
    const float4* B4 = (const float4*)(Bm + (size_t)hh * Nz);
    const float4* C4 = (const float4*)(Cm + (size_t)hh * Nz);
    float4* sp = (float4*)(d_state + ((size_t)(layer * Bz + b) * Hz + h) * Nz);
    double acc = 0.0;
#pragma unroll
    for (int q = 0; q < 4; q++) {
        float4 sv = sp[q];
        float4 av = A4[q], bv = B4[q], cv = C4[q];
        sv.x = __fadd_rn(__fmul_rn(av.x, sv.x), __fmul_rn(bv.x, xd)); acc += (double)sv.x * (double)cv.x;
        sv.y = __fadd_rn(__fmul_rn(av.y, sv.y), __fmul_rn(bv.y, xd)); acc += (double)sv.y * (double)cv.y;
        sv.z = __fadd_rn(__fmul_rn(av.z, sv.z), __fmul_rn(bv.z, xd)); acc += (double)sv.z * (double)cv.z;
        sv.w = __fadd_rn(__fmul_rn(av.w, sv.w), __fmul_rn(bv.w, xd)); acc += (double)sv.w * (double)cv.w;
        sp[q] = sv;
    }
    float yv = __fadd_rn((float)acc, __fmul_rn(Dp[hh], xd));
    d_g[b * Hz + h] = gelu_exact(yv);
}

// ---------------- GEMM: y = g(256x512) @ W(512x512) + bias ----------------
// tiles 16(M) x 64(N), Kt=32, 128 threads; fp32 tile-partials + 2sum-compensated cross-tile accum
__global__ void gemm_kernel(const float* __restrict__ W, const float* __restrict__ bias) {
    __shared__ float As[16][33];
    __shared__ float Bs[32][64];
    int tid = threadIdx.x;
    int bx = blockIdx.x, by = blockIdx.y;
    int tn = tid & 15, tm = tid >> 4;
    int arow = tid >> 3, ac4 = (tid & 7) * 4;
    float s[8], e[8];
#pragma unroll
    for (int j = 0; j < 8; j++) { s[j] = 0.f; e[j] = 0.f; }
    for (int k0 = 0; k0 < Hz; k0 += 32) {
        float4 ga = *(const float4*)&d_g[(by * 16 + arow) * Hz + k0 + ac4];
        As[arow][ac4] = ga.x; As[arow][ac4 + 1] = ga.y;
        As[arow][ac4 + 2] = ga.z; As[arow][ac4 + 3] = ga.w;
#pragma unroll
        for (int j = 0; j < 4; j++) {
            int fi = tid + 128 * j;
            int r = fi >> 4, cc = (fi & 15) * 4;
            *(float4*)&Bs[r][cc] = *(const float4*)&W[(size_t)(k0 + r) * Hz + bx * 64 + cc];
        }
        __syncthreads();
        float p[8];
#pragma unroll
        for (int j = 0; j < 8; j++) p[j] = 0.f;
#pragma unroll
        for (int k = 0; k < 32; k++) {
            float a0 = As[tm * 2][k];
            float a1 = As[tm * 2 + 1][k];
            float4 bv = *(float4*)&Bs[k][tn * 4];
            p[0] += a0 * bv.x; p[1] += a0 * bv.y; p[2] += a0 * bv.z; p[3] += a0 * bv.w;
            p[4] += a1 * bv.x; p[5] += a1 * bv.y; p[6] += a1 * bv.z; p[7] += a1 * bv.w;
        }
        __syncthreads();
#pragma unroll
        for (int j = 0; j < 8; j++) twosum(s[j], e[j], p[j]);
    }
    int m0 = by * 16 + tm * 2, n0 = bx * 64 + tn * 4;
#pragma unroll
    for (int j = 0; j < 8; j++) {
        int mm = m0 + (j >> 2), nn = n0 + (j & 3);
        d_y[mm * Hz + nn] = __fadd_rn(__fadd_rn(s[j], e[j]), bias[nn]);
    }
}

// ---------------- head: LN_1 + logits + fp32-sigmoid argmax + ctx + out + flag ----------------
__global__ void head_kernel(int step, int resMode,
                            const float* __restrict__ lng, const float* __restrict__ lnb,
                            const float* __restrict__ hW, const float* __restrict__ hb,
                            float* __restrict__ out) {
    int b = blockIdx.x, h = threadIdx.x;
    __shared__ double redd[16];
    __shared__ float ts[Hz];
    __shared__ float logits[ODz];   // fp32 logits (reference pipeline)
    __shared__ int ptrS;
    float y = d_y[b * Hz + h];
    float res = resMode ? d_dpTable[d_flag[b] * Hz + h] : y;
    float xd = ln_norm(__fadd_rn(y, res), lng[Hz + h], lnb[Hz + h], redd, h);  // ln layer 1
    float ctx = d_ctx[b * Hz + h];
    float t = __fadd_rn(xd, ctx);
    ts[h] = t;
    __syncthreads();
    int wid = h >> 5, lane = h & 31;
    if (wid < ODz) {
        double sd = 0.0;  // exact central value of the fp32 dot
        for (int j = lane; j < Hz; j += 32) sd += (double)ts[j] * (double)hW[j * ODz + wid];
#pragma unroll
        for (int o = 16; o > 0; o >>= 1) sd += __shfl_xor_sync(0xffffffffu, sd, o);
        if (lane == 0) logits[wid] = __fadd_rn((float)sd, hb[wid]);
    }
    __syncthreads();
    bool is_out = (step & 1) == 0;
    if (!is_out) {
        if (h == 0) {
            // argmax over fp32 sigmoids (fp32 exp pipeline): saturated ties at
            // exactly 1.0f resolve to the FIRST index, like jnp.argmax.
            int best = 0;
            float bv = sigmoid_ref(logits[3]);
#pragma unroll
            for (int k = 1; k < 6; k++) {
                float pv = sigmoid_ref(logits[3 + k]);
                if (pv > bv) { bv = pv; best = k; }
            }
            ptrS = best;
        }
        __syncthreads();
        float ev = d_encoded[((size_t)b * Sz + ptrS) * Hz + h];
        d_ctx[b * Hz + h] = __fadd_rn(ctx, ev);
        ts[h] = __fadd_rn(t, ev);
        __syncthreads();
        if (wid < ODz) {
            double sd = 0.0;
            for (int j = lane; j < Hz; j += 32) sd += (double)ts[j] * (double)hW[j * ODz + wid];
#pragma unroll
            for (int o = 16; o > 0; o >>= 1) sd += __shfl_xor_sync(0xffffffffu, sd, o);
            if (lane == 0) logits[wid] = __fadd_rn((float)sd, hb[wid]);
        }
        __syncthreads();
    }
    if (h < ODz) out[((size_t)b * Tz + step) * ODz + h] = sigmoid_ref(logits[h]);
    if (h == 0) {
        // next dec_in: even step -> [c,1,0] with c = (fp32 sigmoid(l0) > 0.5f); odd -> [0,0,1]
        int c = (sigmoid_ref(logits[0]) > 0.5f) ? 1 : 0;
        d_flag[b] = is_out ? (2 | c) : 0;
    }
}

// ---------------- launch ----------------
extern "C" void kernel_launch(void* const* d_in, const int* in_sizes, int n_in,
                              void* d_out, int out_size) {
    const float* input_seq = (const float*)d_in[0];
    // d_in[1] = autoregressive_steps (unused; T fixed at 63 by OUT_BITS)
    const float* in_W = (const float*)d_in[2];
    const float* in_b = (const float*)d_in[3];
    const float* A    = (const float*)d_in[4];
    const float* Bm   = (const float*)d_in[5];
    const float* Cm   = (const float*)d_in[6];
    const float* Dp   = (const float*)d_in[7];
    const float* outW = (const float*)d_in[8];
    const float* outb = (const float*)d_in[9];
    const float* lng  = (const float*)d_in[10];
    const float* lnb  = (const float*)d_in[11];
    const float* hW   = (const float*)d_in[12];
    const float* hb   = (const float*)d_in[13];
    float* out = (float*)d_out;

    init_kernel<<<(Lz * Bz * Hz * Nz) / 256, 256>>>(in_W, in_b);
    encode_kernel<<<(Bz * Sz * Hz) / 256, 256>>>(input_seq, in_W, in_b);

    dim3 ggrid(Hz / 64, Bz / 16);  // 8 x 16 = 128 CTAs
    for (int step = 0; step < Tz; step++) {
        int r0 = (step == 0) ? 1 : 0;
        state_kernel<<<Bz, Hz>>>(0, 0, 0, A, Bm, Cm, Dp, lng, lnb);
        gemm_kernel<<<ggrid, 128>>>(outW, outb);
        state_kernel<<<Bz, Hz>>>(1, 1, r0, A, Bm, Cm, Dp, lng, lnb);
        gemm_kernel<<<ggrid, 128>>>(outW + (size_t)Hz * Hz, outb + Hz);
        head_kernel<<<Bz, Hz>>>(step, r0, lng, lnb, hW, hb, out);
    }
}

// round 12
// speedup vs baseline: 1.3269x; 1.3269x over previous
#include <cuda_runtime.h>
#include <math.h>
#include <stdint.h>

#define Bz 256
#define Sz 64
#define Hz 512
#define Nz 16
#define Lz 2
#define Tz 63
#define ODz 9
#define NCTA 128
#define NTHR 256

// ---------------- device-global scratch (no allocation allowed) ----------------
__device__ float d_encoded[(size_t)Bz * Sz * Hz];     // 33.5 MB
__device__ float d_state[(size_t)Lz * Bz * Hz * Nz];  // 16.8 MB
__device__ float d_g[Bz * Hz];
__device__ float d_y[Bz * Hz];
__device__ unsigned d_barc;

// ---------------- smem layout offsets (bytes) ----------------
#define OFF_WS   0                       // [2][512][32] f32 = 131072
#define OFF_AS   131072                  // [32][516] f32 = 66048
#define OFF_DP   197120                  // [4][512] f32 = 8192
#define OFF_CTX  205312                  // [2][512] f32 = 4096
#define OFF_TS   209408                  // [512] f32 = 2048
#define OFF_RED  211456                  // [16] f64 = 128
#define OFF_LG   211584                  // [9] f32 = 36 (pad 64)
#define OFF_MISC 211648                  // int[4]
#define SMEM_SZ  211712

// ---------------- helpers ----------------
// Grid barrier with a timeout escape hatch: in normal operation (all 128 CTAs
// co-resident, 1 CTA/SM on 148 SMs) the spin lasts <~50us and the timeout is
// never hit. If co-residency is ever violated, we break out after ~25ms so the
// kernel TERMINATES (producing wrong results -> clean rel_err failure with
// diagnostics) instead of hanging and killing the container.
__device__ __forceinline__ void gsync(unsigned target) {
    __syncthreads();
    if (threadIdx.x == 0) {
        __threadfence();
        atomicAdd(&d_barc, 1u);
        long long t0 = clock64();
        while (*((volatile unsigned*)&d_barc) < target) {
            if (clock64() - t0 > 40000000ll) break;  // ~25ms escape hatch
        }
        __threadfence();
    }
    __syncthreads();
}

// block-wide fp64 sum over 256 threads (one double per thread)
__device__ __forceinline__ double bsum256(double v, double* red) {
    int t = threadIdx.x, w = t >> 5, lane = t & 31;
#pragma unroll
    for (int o = 16; o > 0; o >>= 1) v += __shfl_xor_sync(0xffffffffu, v, o);
    if (lane == 0) red[w] = v;
    __syncthreads();
    if (t < 32) {
        double r = (lane < 8) ? red[lane] : 0.0;
#pragma unroll
        for (int o = 4; o > 0; o >>= 1) r += __shfl_xor_sync(0xffffffffu, r, o);
        if (lane == 0) red[0] = r;
    }
    __syncthreads();
    double r = red[0];
    __syncthreads();
    return r;
}

// two-pass fp64 LayerNorm over 512 values held 2-per-thread
__device__ __forceinline__ void ln2(float v0, float v1, float g0, float g1,
                                    float b0, float b1, float& o0, float& o1, double* red) {
    double m = bsum256((double)v0 + (double)v1, red) * (1.0 / Hz);
    double dd0 = (double)v0 - m, dd1 = (double)v1 - m;
    double var = bsum256(dd0 * dd0 + dd1 * dd1, red) * (1.0 / Hz);
    double sc = 1.0 / sqrt(var + 1e-5);
    o0 = (float)(dd0 * sc * (double)g0 + (double)b0);
    o1 = (float)(dd1 * sc * (double)g1 + (double)b1);
}

__device__ __forceinline__ float gelu_exact(float x) {
    return 0.5f * x * (1.0f + erff(x * 0.7071067811865476f));
}

// fp32-exp sigmoid pipeline (matches XLA fp32; saturates to exactly 1.0f for x>~16.64)
__device__ __forceinline__ float sigmoid_ref(float x) {
    return 1.0f / (1.0f + expf(-x));
}

// S4 recurrence + output dot for one (layer, b, h); writes gelu(y) to d_g
__device__ __forceinline__ void s4upd(int layer, int b, int h, float xd,
                                      const float* __restrict__ A, const float* __restrict__ Bm,
                                      const float* __restrict__ Cm, const float* __restrict__ Dp) {
    int hh = layer * Hz + h;
    const float4* A4 = (const float4*)(A + (size_t)hh * Nz);
    const float4* B4 = (const float4*)(Bm + (size_t)hh * Nz);
    const float4* C4 = (const float4*)(Cm + (size_t)hh * Nz);
    float4* sp = (float4*)(d_state + ((size_t)(layer * Bz + b) * Hz + h) * Nz);
    float acc = 0.f;
#pragma unroll
    for (int q = 0; q < 4; q++) {
        float4 sv = sp[q];
        float4 av = A4[q], bv = B4[q], cv = C4[q];
        sv.x = __fadd_rn(__fmul_rn(av.x, sv.x), __fmul_rn(bv.x, xd)); acc = fmaf(sv.x, cv.x, acc);
        sv.y = __fadd_rn(__fmul_rn(av.y, sv.y), __fmul_rn(bv.y, xd)); acc = fmaf(sv.y, cv.y, acc);
        sv.z = __fadd_rn(__fmul_rn(av.z, sv.z), __fmul_rn(bv.z, xd)); acc = fmaf(sv.z, cv.z, acc);
        sv.w = __fadd_rn(__fmul_rn(av.w, sv.w), __fmul_rn(bv.w, xd)); acc = fmaf(sv.w, cv.w, acc);
        sp[q] = sv;
    }
    float yv = __fadd_rn(acc, __fmul_rn(Dp[hh], xd));
    d_g[b * Hz + h] = gelu_exact(yv);
}

// GEMM phase: out tile (m0..m0+31) x (n0..n0+31) of y = g @ W + bias.
// W slice in smem, A tile staged to smem, packed f32x2 FMA, fp64 chunk combine.
__device__ __forceinline__ void gemm_phase(const float* __restrict__ Wl, float* __restrict__ As,
                                           const float* __restrict__ bias,
                                           int m0, int n0, int tr, int tc) {
    for (int i = threadIdx.x; i < 4096; i += NTHR) {
        int r = i >> 7, c4 = (i & 127) * 4;
        *(float4*)&As[r * 516 + c4] = *(const float4*)&d_g[(m0 + r) * Hz + c4];
    }
    __syncthreads();
    double dacc0 = 0.0, dacc1 = 0.0, dacc2 = 0.0, dacc3 = 0.0;
    const float* arow = &As[tr * 516];
    for (int k0 = 0; k0 < Hz; k0 += 64) {
        unsigned long long p01 = 0ull, p23 = 0ull;
#pragma unroll 4
        for (int k = k0; k < k0 + 64; k += 4) {
            float4 av = *(const float4*)&arow[k];
#pragma unroll
            for (int j = 0; j < 4; j++) {
                float a = (j == 0) ? av.x : (j == 1) ? av.y : (j == 2) ? av.z : av.w;
                unsigned long long a2;
                asm("mov.b64 %0, {%1, %1};" : "=l"(a2) : "f"(a));
                unsigned long long w01 = *(const unsigned long long*)&Wl[(k + j) * 32 + tc];
                unsigned long long w23 = *(const unsigned long long*)&Wl[(k + j) * 32 + tc + 2];
                asm("fma.rn.f32x2 %0, %1, %2, %0;" : "+l"(p01) : "l"(a2), "l"(w01));
                asm("fma.rn.f32x2 %0, %1, %2, %0;" : "+l"(p23) : "l"(a2), "l"(w23));
            }
        }
        float lo, hi;
        asm("mov.b64 {%0, %1}, %2;" : "=f"(lo), "=f"(hi) : "l"(p01));
        dacc0 += (double)lo; dacc1 += (double)hi;
        asm("mov.b64 {%0, %1}, %2;" : "=f"(lo), "=f"(hi) : "l"(p23));
        dacc2 += (double)lo; dacc3 += (double)hi;
    }
    int row = (m0 + tr) * Hz + n0 + tc;
    d_y[row]     = __fadd_rn((float)dacc0, bias[n0 + tc]);
    d_y[row + 1] = __fadd_rn((float)dacc1, bias[n0 + tc + 1]);
    d_y[row + 2] = __fadd_rn((float)dacc2, bias[n0 + tc + 2]);
    d_y[row + 3] = __fadd_rn((float)dacc3, bias[n0 + tc + 3]);
}

// 9 head logits from ts_s (fp64 dot, lane-strided + shuffle — same order as passing kernel)
__device__ __forceinline__ void logits9(const float* __restrict__ ts_s,
                                        const float* __restrict__ hW, const float* __restrict__ hb,
                                        float* __restrict__ logit_s) {
    int t = threadIdx.x, w = t >> 5, lane = t & 31;
    for (int j = w; j < ODz; j += 8) {
        double sd = 0.0;
        for (int i = lane; i < Hz; i += 32) sd += (double)ts_s[i] * (double)hW[i * ODz + j];
#pragma unroll
        for (int o = 16; o > 0; o >>= 1) sd += __shfl_xor_sync(0xffffffffu, sd, o);
        if (lane == 0) logit_s[j] = __fadd_rn((float)sd, hb[j]);
    }
}

// ---------------- init node: zero state + barrier counter ----------------
__global__ void init_k() {
    size_t i = (size_t)blockIdx.x * 1024 + threadIdx.x;
    if (i < (size_t)Lz * Bz * Hz * Nz) d_state[i] = 0.f;
    if (i == 0) d_barc = 0u;
}

// ---------------- the persistent kernel ----------------
__global__ void __launch_bounds__(NTHR, 1) persist_k(
    const float* __restrict__ input_seq,
    const float* __restrict__ in_W, const float* __restrict__ in_b,
    const float* __restrict__ A, const float* __restrict__ Bm,
    const float* __restrict__ Cm, const float* __restrict__ Dp,
    const float* __restrict__ outW, const float* __restrict__ outb,
    const float* __restrict__ lng, const float* __restrict__ lnb,
    const float* __restrict__ hW, const float* __restrict__ hb,
    float* __restrict__ out) {
    extern __shared__ char sm[];
    float*  Ws      = (float*)(sm + OFF_WS);    // [2][512][32]
    float*  As      = (float*)(sm + OFF_AS);    // [32][516]
    float*  dp_s    = (float*)(sm + OFF_DP);    // [4][512]
    float*  ctx_s   = (float*)(sm + OFF_CTX);   // [2][512]
    float*  ts_s    = (float*)(sm + OFF_TS);    // [512]
    double* red_s   = (double*)(sm + OFF_RED);  // [16]
    float*  logit_s = (float*)(sm + OFF_LG);    // [9]
    int*    misc    = (int*)(sm + OFF_MISC);    // [0]=ptr, [1]=flag_b0, [2]=flag_b1

    const int c = blockIdx.x, t = threadIdx.x;
    const int mi = c >> 4, ni = c & 15;
    const int m0 = mi * 32, n0 = ni * 32;
    const int tr = t >> 3, tc = (t & 7) * 4;

    // ---- entry: cache W slices, dp table, ctx, flags; encode ----
    for (int l = 0; l < 2; l++)
        for (int i = t; i < 4096; i += NTHR) {
            int k = i >> 3, nq = (i & 7) * 4;
            *(float4*)&Ws[l * 16384 + k * 32 + nq] =
                *(const float4*)&outW[(size_t)l * Hz * Hz + (size_t)k * Hz + n0 + nq];
        }
    for (int i = t; i < 4 * Hz; i += NTHR) {
        int v = i >> 9, h = i & 511;
        float cc = (float)(v & 1), t0 = (float)((v >> 1) & 1);
        float s = __fadd_rn(__fadd_rn(__fmul_rn(cc, in_W[h]), __fmul_rn(t0, in_W[Hz + h])),
                            __fmul_rn(__fsub_rn(1.f, t0), in_W[2 * Hz + h]));
        dp_s[i] = __fadd_rn(s, in_b[h]);
    }
    ctx_s[t] = 0.f; ctx_s[t + 256] = 0.f; ctx_s[512 + t] = 0.f; ctx_s[512 + t + 256] = 0.f;
    if (t == 0) { misc[1] = 0; misc[2] = 0; }
    for (size_t i = (size_t)c * NTHR + t; i < (size_t)Bz * Sz * Hz; i += (size_t)NCTA * NTHR) {
        int h = (int)(i & 511);
        size_t bs = i >> 9;
        const float* p = input_seq + bs * 3;
        float s = __fadd_rn(__fadd_rn(__fmul_rn(p[0], in_W[h]), __fmul_rn(p[1], in_W[Hz + h])),
                            __fmul_rn(p[2], in_W[2 * Hz + h]));
        d_encoded[i] = __fadd_rn(s, in_b[h]);
    }
    __syncthreads();

    unsigned ep = 0;
    const int b0 = c * 2;

    for (int step = 0; step < Tz; step++) {
        // ---- phase A: state layer 0 (xd = dp[flag]) -> d_g ----
        for (int bb = 0; bb < 2; bb++) {
            int b = b0 + bb;
            int fl = misc[1 + bb];
            s4upd(0, b, t,       dp_s[fl * Hz + t],       A, Bm, Cm, Dp);
            s4upd(0, b, t + 256, dp_s[fl * Hz + t + 256], A, Bm, Cm, Dp);
        }
        gsync(++ep * NCTA);

        // ---- phase B: GEMM layer 0 ----
        gemm_phase(Ws, As, outb, m0, n0, tr, tc);
        gsync(++ep * NCTA);

        // ---- phase C: state layer 1 (xd = LN0(y+res)) -> d_g ----
        for (int bb = 0; bb < 2; bb++) {
            int b = b0 + bb;
            int fl = misc[1 + bb];
            float y0 = d_y[b * Hz + t], y1 = d_y[b * Hz + t + 256];
            float r0 = step ? y0 : dp_s[fl * Hz + t];
            float r1 = step ? y1 : dp_s[fl * Hz + t + 256];
            float x0, x1;
            ln2(__fadd_rn(y0, r0), __fadd_rn(y1, r1),
                lng[t], lng[t + 256], lnb[t], lnb[t + 256], x0, x1, red_s);
            s4upd(1, b, t, x0, A, Bm, Cm, Dp);
            s4upd(1, b, t + 256, x1, A, Bm, Cm, Dp);
        }
        gsync(++ep * NCTA);

        // ---- phase D: GEMM layer 1 ----
        gemm_phase(Ws + 16384, As, outb + Hz, m0, n0, tr, tc);
        gsync(++ep * NCTA);

        // ---- phase E: head (LN1, logits, sigmoid-argmax, ctx, out, flags) ----
        bool is_out = (step & 1) == 0;
        for (int bb = 0; bb < 2; bb++) {
            int b = b0 + bb;
            int fl = misc[1 + bb];
            float y0 = d_y[b * Hz + t], y1 = d_y[b * Hz + t + 256];
            float r0 = step ? y0 : dp_s[fl * Hz + t];
            float r1 = step ? y1 : dp_s[fl * Hz + t + 256];
            float x0, x1;
            ln2(__fadd_rn(y0, r0), __fadd_rn(y1, r1),
                lng[Hz + t], lng[Hz + t + 256], lnb[Hz + t], lnb[Hz + t + 256], x0, x1, red_s);
            float c0 = ctx_s[bb * Hz + t], c1 = ctx_s[bb * Hz + t + 256];
            float t0v = __fadd_rn(x0, c0), t1v = __fadd_rn(x1, c1);
            ts_s[t] = t0v; ts_s[t + 256] = t1v;
            __syncthreads();
            logits9(ts_s, hW, hb, logit_s);
            __syncthreads();
            if (!is_out) {
                if (t == 0) {
                    int best = 0;
                    float bv = sigmoid_ref(logit_s[3]);
#pragma unroll
                    for (int k = 1; k < 6; k++) {
                        float pv = sigmoid_ref(logit_s[3 + k]);
                        if (pv > bv) { bv = pv; best = k; }
                    }
                    misc[0] = best;
                }
                __syncthreads();
                int ptr = misc[0];
                float e0 = d_encoded[((size_t)b * Sz + ptr) * Hz + t];
                float e1 = d_encoded[((size_t)b * Sz + ptr) * Hz + t + 256];
                ctx_s[bb * Hz + t] = __fadd_rn(c0, e0);
                ctx_s[bb * Hz + t + 256] = __fadd_rn(c1, e1);
                ts_s[t] = __fadd_rn(t0v, e0); ts_s[t + 256] = __fadd_rn(t1v, e1);
                __syncthreads();
                logits9(ts_s, hW, hb, logit_s);
                __syncthreads();
            }
            if (t < ODz) out[((size_t)b * Tz + step) * ODz + t] = sigmoid_ref(logit_s[t]);
            if (t == 0) {
                int cbit = (sigmoid_ref(logit_s[0]) > 0.5f) ? 1 : 0;
                misc[1 + bb] = is_out ? (2 | cbit) : 0;
            }
            __syncthreads();
        }
        // E -> next A is CTA-local (flags in smem); g republished at next A-barrier
    }
}

// ---------------- launch ----------------
extern "C" void kernel_launch(void* const* d_in, const int* in_sizes, int n_in,
                              void* d_out, int out_size) {
    const float* input_seq = (const float*)d_in[0];
    // d_in[1] = autoregressive_steps (unused; T fixed at 63 by OUT_BITS)
    const float* in_W = (const float*)d_in[2];
    const float* in_b = (const float*)d_in[3];
    const float* A    = (const float*)d_in[4];
    const float* Bm   = (const float*)d_in[5];
    const float* Cm   = (const float*)d_in[6];
    const float* Dp   = (const float*)d_in[7];
    const float* outW = (const float*)d_in[8];
    const float* outb = (const float*)d_in[9];
    const float* lng  = (const float*)d_in[10];
    const float* lnb  = (const float*)d_in[11];
    const float* hW   = (const float*)d_in[12];
    const float* hb   = (const float*)d_in[13];
    float* out = (float*)d_out;

    // unconditional (idempotent, deterministic, capture-safe host API call)
    cudaFuncSetAttribute(persist_k, cudaFuncAttributeMaxDynamicSharedMemorySize, SMEM_SZ);

    init_k<<<4096, 1024>>>();
    persist_k<<<NCTA, NTHR, SMEM_SZ>>>(input_seq, in_W, in_b, A, Bm, Cm, Dp,
                                       outW, outb, lng, lnb, hW, hb, out);
}

// round 16
// speedup vs baseline: 1.5395x; 1.1603x over previous
#include <cuda_runtime.h>
#include <math.h>
#include <stdint.h>

#define Bz 256
#define Sz 64
#define Hz 512
#define Nz 16
#define Lz 2
#define Tz 63
#define ODz 9
#define NCTA 128
#define NTHR 256

// ---------------- device-global scratch (no allocation allowed) ----------------
__device__ float d_encoded[(size_t)Bz * Sz * Hz];     // 33.5 MB
__device__ float d_state[(size_t)Lz * Bz * Hz * Nz];  // 16.8 MB
__device__ float d_g[Bz * Hz];
__device__ float d_y[Bz * Hz];
__device__ unsigned d_barc;

// ---------------- smem layout offsets (bytes) ----------------
#define OFF_WS   0                       // [2][512][32] f32 = 131072
#define OFF_AS   131072                  // [32][516] f32 = 66048 (gemm staging; reused as hWt[9][512] in E)
#define OFF_DP   197120                  // [4][512] f32 = 8192
#define OFF_CTX  205312                  // [2][512] f32 = 4096
#define OFF_TS   209408                  // [2][512] f32 = 4096
#define OFF_RED  213504                  // [8] f32 (pad 128)
#define OFF_LG   213632                  // [2][16] f32 = 128
#define OFF_MISC 213760                  // int[8]: [1],[2]=flags  [3],[4]=ptrs
#define SMEM_SZ  213888

// ---------------- helpers ----------------
// Grid barrier with a timeout escape hatch (never fires in normal co-resident
// operation; converts a co-residency violation into a terminating wrong-answer
// instead of a container-killing hang).
__device__ __forceinline__ void gsync(unsigned target) {
    __syncthreads();
    if (threadIdx.x == 0) {
        __threadfence();
        atomicAdd(&d_barc, 1u);
        long long t0 = clock64();
        while (*((volatile unsigned*)&d_barc) < target) {
            if (clock64() - t0 > 40000000ll) break;  // ~25ms escape hatch
        }
        __threadfence();
    }
    __syncthreads();
}

// fp32 sum over one 128-thread group (4 warps); red = shared float[8]
__device__ __forceinline__ float gsum128(float v, float* red, int group, int gtid) {
    int w = gtid >> 5, lane = gtid & 31;
#pragma unroll
    for (int o = 16; o > 0; o >>= 1) v += __shfl_xor_sync(0xffffffffu, v, o);
    if (lane == 0) red[group * 4 + w] = v;
    __syncthreads();
    float r = (red[group * 4] + red[group * 4 + 1]) + (red[group * 4 + 2] + red[group * 4 + 3]);
    __syncthreads();
    return r;
}

// two-pass fp32 LayerNorm over 512 values held 4-per-thread within a 128-thread group
__device__ __forceinline__ float4 ln4(float4 v, float4 gg, float4 bb,
                                      float* red, int group, int gtid) {
    float m = gsum128((v.x + v.y) + (v.z + v.w), red, group, gtid) * (1.0f / Hz);
    float4 d = make_float4(v.x - m, v.y - m, v.z - m, v.w - m);
    float var = gsum128((d.x * d.x + d.y * d.y) + (d.z * d.z + d.w * d.w),
                        red, group, gtid) * (1.0f / Hz);
    float sc = rsqrtf(var + 1e-5f);
    return make_float4(fmaf(d.x * sc, gg.x, bb.x), fmaf(d.y * sc, gg.y, bb.y),
                       fmaf(d.z * sc, gg.z, bb.z), fmaf(d.w * sc, gg.w, bb.w));
}

__device__ __forceinline__ float gelu_exact(float x) {
    return 0.5f * x * (1.0f + erff(x * 0.7071067811865476f));
}

// fp32-exp sigmoid pipeline (matches XLA fp32; saturates to exactly 1.0f for x>~16.64)
__device__ __forceinline__ float sigmoid_ref(float x) {
    return 1.0f / (1.0f + expf(-x));
}

// S4 recurrence + output dot for one (layer, b, h) — arithmetic identical to the
// passing round-12 kernel (elementwise mul/add with explicit rn, fp32 fmaf dot).
__device__ __forceinline__ void s4upd(int layer, int b, int h, float xd,
                                      const float* __restrict__ A, const float* __restrict__ Bm,
                                      const float* __restrict__ Cm, const float* __restrict__ Dp) {
    int hh = layer * Hz + h;
    const float4* A4 = (const float4*)(A + (size_t)hh * Nz);
    const float4* B4 = (const float4*)(Bm + (size_t)hh * Nz);
    const float4* C4 = (const float4*)(Cm + (size_t)hh * Nz);
    float4* sp = (float4*)(d_state + ((size_t)(layer * Bz + b) * Hz + h) * Nz);
    float acc = 0.f;
#pragma unroll
    for (int q = 0; q < 4; q++) {
        float4 sv = sp[q];
        float4 av = A4[q], bv = B4[q], cv = C4[q];
        sv.x = __fadd_rn(__fmul_rn(av.x, sv.x), __fmul_rn(bv.x, xd)); acc = fmaf(sv.x, cv.x, acc);
        sv.y = __fadd_rn(__fmul_rn(av.y, sv.y), __fmul_rn(bv.y, xd)); acc = fmaf(sv.y, cv.y, acc);
        sv.z = __fadd_rn(__fmul_rn(av.z, sv.z), __fmul_rn(bv.z, xd)); acc = fmaf(sv.z, cv.z, acc);
        sv.w = __fadd_rn(__fmul_rn(av.w, sv.w), __fmul_rn(bv.w, xd)); acc = fmaf(sv.w, cv.w, acc);
        sp[q] = sv;
    }
    float yv = __fadd_rn(acc, __fmul_rn(Dp[hh], xd));
    d_g[b * Hz + h] = gelu_exact(yv);
}

// GEMM phase: y tile (m0..+31) x (n0..+31), W slice in smem, pure f32x2 FMA accumulation
__device__ __forceinline__ void gemm_phase(const float* __restrict__ Wl, float* __restrict__ As,
                                           const float* __restrict__ bias,
                                           int m0, int n0, int tr, int tc) {
    for (int i = threadIdx.x; i < 4096; i += NTHR) {
        int r = i >> 7, c4 = (i & 127) * 4;
        *(float4*)&As[r * 516 + c4] = *(const float4*)&d_g[(m0 + r) * Hz + c4];
    }
    __syncthreads();
    unsigned long long p01 = 0ull, p23 = 0ull;
    const float* arow = &As[tr * 516];
#pragma unroll 4
    for (int k = 0; k < Hz; k += 4) {
        float4 av = *(const float4*)&arow[k];
#pragma unroll
        for (int j = 0; j < 4; j++) {
            float a = (j == 0) ? av.x : (j == 1) ? av.y : (j == 2) ? av.z : av.w;
            unsigned long long a2;
            asm("mov.b64 %0, {%1, %1};" : "=l"(a2) : "f"(a));
            unsigned long long w01 = *(const unsigned long long*)&Wl[(k + j) * 32 + tc];
            unsigned long long w23 = *(const unsigned long long*)&Wl[(k + j) * 32 + tc + 2];
            asm("fma.rn.f32x2 %0, %1, %2, %0;" : "+l"(p01) : "l"(a2), "l"(w01));
            asm("fma.rn.f32x2 %0, %1, %2, %0;" : "+l"(p23) : "l"(a2), "l"(w23));
        }
    }
    float o0, o1, o2, o3;
    asm("mov.b64 {%0, %1}, %2;" : "=f"(o0), "=f"(o1) : "l"(p01));
    asm("mov.b64 {%0, %1}, %2;" : "=f"(o2), "=f"(o3) : "l"(p23));
    int row = (m0 + tr) * Hz + n0 + tc;
    d_y[row]     = __fadd_rn(o0, bias[n0 + tc]);
    d_y[row + 1] = __fadd_rn(o1, bias[n0 + tc + 1]);
    d_y[row + 2] = __fadd_rn(o2, bias[n0 + tc + 2]);
    d_y[row + 3] = __fadd_rn(o3, bias[n0 + tc + 3]);
}

// one head logit j for one group: fp32 FMA over 512 elems (contiguous float4), warp reduce
__device__ __forceinline__ void logit_one(int j, const float* __restrict__ hWt,
                                          const float* __restrict__ tsg,
                                          const float* __restrict__ hb,
                                          float* __restrict__ lg_grp, int lane) {
    const float4* wv4 = (const float4*)&hWt[j * Hz];
    const float4* tv4 = (const float4*)tsg;
    float a0 = 0.f, a1 = 0.f;
#pragma unroll
    for (int q = 0; q < 4; q++) {
        float4 x = tv4[lane + 32 * q];
        float4 w = wv4[lane + 32 * q];
        a0 = fmaf(x.x, w.x, a0); a1 = fmaf(x.y, w.y, a1);
        a0 = fmaf(x.z, w.z, a0); a1 = fmaf(x.w, w.w, a1);
    }
    float s = a0 + a1;
#pragma unroll
    for (int o = 16; o > 0; o >>= 1) s += __shfl_xor_sync(0xffffffffu, s, o);
    if (lane == 0) lg_grp[j] = __fadd_rn(s, hb[j]);
}

// ---------------- init node: zero state + barrier counter ----------------
__global__ void init_k() {
    size_t i = (size_t)blockIdx.x * 1024 + threadIdx.x;
    if (i < (size_t)Lz * Bz * Hz * Nz) d_state[i] = 0.f;
    if (i == 0) d_barc = 0u;
}

// ---------------- the persistent kernel ----------------
__global__ void __launch_bounds__(NTHR, 1) persist_k(
    const float* __restrict__ input_seq,
    const float* __restrict__ in_W, const float* __restrict__ in_b,
    const float* __restrict__ A, const float* __restrict__ Bm,
    const float* __restrict__ Cm, const float* __restrict__ Dp,
    const float* __restrict__ outW, const float* __restrict__ outb,
    const float* __restrict__ lng, const float* __restrict__ lnb,
    const float* __restrict__ hW, const float* __restrict__ hb,
    float* __restrict__ out) {
    extern __shared__ char sm[];
    float* Ws      = (float*)(sm + OFF_WS);
    float* As      = (float*)(sm + OFF_AS);
    float* dp_s    = (float*)(sm + OFF_DP);
    float* ctx_s   = (float*)(sm + OFF_CTX);
    float* ts_s    = (float*)(sm + OFF_TS);
    float* red_s   = (float*)(sm + OFF_RED);
    float* logit_s = (float*)(sm + OFF_LG);
    int*   misc    = (int*)(sm + OFF_MISC);

    const int c = blockIdx.x, t = threadIdx.x;
    const int mi = c >> 4, ni = c & 15;
    const int m0 = mi * 32, n0 = ni * 32;
    const int tr = t >> 3, tc = (t & 7) * 4;
    const int g = t >> 7, gtid = t & 127;     // 2 groups of 128 threads (one batch each)
    const int h4 = gtid * 4;
    const int b0 = c * 2;
    const int b = b0 + g;

    // ---- entry: cache W slices, dp table, ctx, flags; encode ----
    for (int l = 0; l < 2; l++)
        for (int i = t; i < 4096; i += NTHR) {
            int k = i >> 3, nq = (i & 7) * 4;
            *(float4*)&Ws[l * 16384 + k * 32 + nq] =
                *(const float4*)&outW[(size_t)l * Hz * Hz + (size_t)k * Hz + n0 + nq];
        }
    for (int i = t; i < 4 * Hz; i += NTHR) {
        int v = i >> 9, h = i & 511;
        float cc = (float)(v & 1), t0 = (float)((v >> 1) & 1);
        float s = __fadd_rn(__fadd_rn(__fmul_rn(cc, in_W[h]), __fmul_rn(t0, in_W[Hz + h])),
                            __fmul_rn(__fsub_rn(1.f, t0), in_W[2 * Hz + h]));
        dp_s[i] = __fadd_rn(s, in_b[h]);
    }
    for (int i = t; i < 2 * Hz; i += NTHR) ctx_s[i] = 0.f;
    if (t == 0) { misc[1] = 0; misc[2] = 0; }
    for (size_t i = (size_t)c * NTHR + t; i < (size_t)Bz * Sz * Hz; i += (size_t)NCTA * NTHR) {
        int h = (int)(i & 511);
        size_t bs = i >> 9;
        const float* p = input_seq + bs * 3;
        float s = __fadd_rn(__fadd_rn(__fmul_rn(p[0], in_W[h]), __fmul_rn(p[1], in_W[Hz + h])),
                            __fmul_rn(p[2], in_W[2 * Hz + h]));
        d_encoded[i] = __fadd_rn(s, in_b[h]);
    }
    __syncthreads();

    unsigned ep = 0;
    for (int step = 0; step < Tz; step++) {
        // ---- phase A: state layer 0 (xd = dp[flag]) -> d_g (group-parallel) ----
        {
            int fl = misc[1 + g];
            float4 xd = *(const float4*)&dp_s[fl * Hz + h4];
            s4upd(0, b, h4,     xd.x, A, Bm, Cm, Dp);
            s4upd(0, b, h4 + 1, xd.y, A, Bm, Cm, Dp);
            s4upd(0, b, h4 + 2, xd.z, A, Bm, Cm, Dp);
            s4upd(0, b, h4 + 3, xd.w, A, Bm, Cm, Dp);
        }
        gsync(++ep * NCTA);

        // ---- phase B: GEMM layer 0 ----
        gemm_phase(Ws, As, outb, m0, n0, tr, tc);
        gsync(++ep * NCTA);

        // ---- phase C: state layer 1 (xd = LN0(y+res)) -> d_g (group-parallel) ----
        {
            int fl = misc[1 + g];
            float4 yv = *(const float4*)&d_y[b * Hz + h4];
            float4 dv = *(const float4*)&dp_s[fl * Hz + h4];
            float4 rv = step ? yv : dv;
            float4 sv = make_float4(__fadd_rn(yv.x, rv.x), __fadd_rn(yv.y, rv.y),
                                    __fadd_rn(yv.z, rv.z), __fadd_rn(yv.w, rv.w));
            float4 gg = *(const float4*)&lng[h4];
            float4 bb = *(const float4*)&lnb[h4];
            float4 xd = ln4(sv, gg, bb, red_s, g, gtid);
            s4upd(1, b, h4,     xd.x, A, Bm, Cm, Dp);
            s4upd(1, b, h4 + 1, xd.y, A, Bm, Cm, Dp);
            s4upd(1, b, h4 + 2, xd.z, A, Bm, Cm, Dp);
            s4upd(1, b, h4 + 3, xd.w, A, Bm, Cm, Dp);
        }
        gsync(++ep * NCTA);

        // ---- phase D: GEMM layer 1 ----
        gemm_phase(Ws + 16384, As, outb + Hz, m0, n0, tr, tc);
        gsync(++ep * NCTA);

        // ---- phase E: head (group-parallel over the CTA's 2 batches) ----
        {
            float* hWt = As;  // As is dead until next gemm; reuse for transposed head weights
            for (int i = t; i < ODz * Hz; i += NTHR) hWt[i] = hW[(i & (Hz - 1)) * ODz + (i >> 9)];
            int fl = misc[1 + g];
            float4 yv = *(const float4*)&d_y[b * Hz + h4];
            float4 dv = *(const float4*)&dp_s[fl * Hz + h4];
            float4 rv = step ? yv : dv;
            float4 sv = make_float4(__fadd_rn(yv.x, rv.x), __fadd_rn(yv.y, rv.y),
                                    __fadd_rn(yv.z, rv.z), __fadd_rn(yv.w, rv.w));
            float4 gg = *(const float4*)&lng[Hz + h4];
            float4 bb = *(const float4*)&lnb[Hz + h4];
            float4 xd = ln4(sv, gg, bb, red_s, g, gtid);   // contains syncthreads (orders hWt too)
            float4 cv = *(const float4*)&ctx_s[g * Hz + h4];
            float4 t4 = make_float4(__fadd_rn(xd.x, cv.x), __fadd_rn(xd.y, cv.y),
                                    __fadd_rn(xd.z, cv.z), __fadd_rn(xd.w, cv.w));
            *(float4*)&ts_s[g * Hz + h4] = t4;
            __syncthreads();
            int w = gtid >> 5, lane = gtid & 31;
            float* lg_grp = &logit_s[g * 16];
            const float* tsg = &ts_s[g * Hz];
            logit_one(w, hWt, tsg, hb, lg_grp, lane);
            logit_one(w + 4, hWt, tsg, hb, lg_grp, lane);
            if (w == 0) logit_one(8, hWt, tsg, hb, lg_grp, lane);
            __syncthreads();
            bool is_out = (step & 1) == 0;
            if (!is_out) {
                if (gtid == 0) {
                    // argmax over fp32 sigmoids: saturated ties at 1.0f -> first index
                    int best = 0;
                    float bv = sigmoid_ref(lg_grp[3]);
#pragma unroll
                    for (int k = 1; k < 6; k++) {
                        float pv = sigmoid_ref(lg_grp[3 + k]);
                        if (pv > bv) { bv = pv; best = k; }
                    }
                    misc[3 + g] = best;
                }
                __syncthreads();
                int ptr = misc[3 + g];
                float4 ev = *(const float4*)&d_encoded[((size_t)b * Sz + ptr) * Hz + h4];
                *(float4*)&ctx_s[g * Hz + h4] =
                    make_float4(__fadd_rn(cv.x, ev.x), __fadd_rn(cv.y, ev.y),
                                __fadd_rn(cv.z, ev.z), __fadd_rn(cv.w, ev.w));
                *(float4*)&ts_s[g * Hz + h4] =
                    make_float4(__fadd_rn(t4.x, ev.x), __fadd_rn(t4.y, ev.y),
                                __fadd_rn(t4.z, ev.z), __fadd_rn(t4.w, ev.w));
                __syncthreads();
                logit_one(w, hWt, tsg, hb, lg_grp, lane);
                logit_one(w + 4, hWt, tsg, hb, lg_grp, lane);
                if (w == 0) logit_one(8, hWt, tsg, hb, lg_grp, lane);
                __syncthreads();
            }
            if (gtid < ODz) out[((size_t)b * Tz + step) * ODz + gtid] = sigmoid_ref(lg_grp[gtid]);
            if (gtid == 0) {
                int cbit = (sigmoid_ref(lg_grp[0]) > 0.5f) ? 1 : 0;
                misc[1 + g] = is_out ? (2 | cbit) : 0;
            }
            __syncthreads();
        }
        // E -> next A is CTA-local (flags in smem)
    }
}

// ---------------- launch ----------------
extern "C" void kernel_launch(void* const* d_in, const int* in_sizes, int n_in,
                              void* d_out, int out_size) {
    const float* input_seq = (const float*)d_in[0];
    // d_in[1] = autoregressive_steps (unused; T fixed at 63 by OUT_BITS)
    const float* in_W = (const float*)d_in[2];
    const float* in_b = (const float*)d_in[3];
    const float* A    = (const float*)d_in[4];
    const float* Bm   = (const float*)d_in[5];
    const float* Cm   = (const float*)d_in[6];
    const float* Dp   = (const float*)d_in[7];
    const float* outW = (const float*)d_in[8];
    const float* outb = (const float*)d_in[9];
    const float* lng  = (const float*)d_in[10];
    const float* lnb  = (const float*)d_in[11];
    const float* hW   = (const float*)d_in[12];
    const float* hb   = (const float*)d_in[13];
    float* out = (float*)d_out;

    cudaFuncSetAttribute(persist_k, cudaFuncAttributeMaxDynamicSharedMemorySize, SMEM_SZ);

    init_k<<<4096, 1024>>>();
    persist_k<<<NCTA, NTHR, SMEM_SZ>>>(input_seq, in_W, in_b, A, Bm, Cm, Dp,
                                       outW, outb, lng, lnb, hW, hb, out);
}